// round 2
// baseline (speedup 1.0000x reference)
#include <cuda_runtime.h>
#include <math.h>

#define NROWS 16384
#define HDIM  4096
#define NEXP  64
#define TOPK  2
#define MT    64     // rows per block
#define KC    64     // k-chunk
#define NTHR  256

// Tile: 64 rows x 64 experts per block. Each thread owns a 4x4 register tile:
//   te = tid & 15  -> expert quad (4 consecutive experts, te*4..te*4+3)
//   tr = tid >> 4  -> row quad    (4 consecutive rows,   tr*4..tr*4+3)
// Inner loop per k: 1 LDS.128 (W, transposed layout) + 4 broadcast LDS (x) -> 16 FFMA.
__global__ void __launch_bounds__(NTHR)
router_kernel(const float* __restrict__ x, const float* __restrict__ W,
              float* __restrict__ scores, float* __restrict__ wout,
              float* __restrict__ iout)
{
    // x chunk padded to 68 floats/row: row stride 272B (16B aligned for float4
    // stores, +4 words kills broadcast-pair bank conflicts on scalar reads).
    __shared__ float xs[MT][KC + 4];
    __shared__ float ws[KC][NEXP];   // W transposed: ws[k][e]

    const int tid  = threadIdx.x;
    const int row0 = blockIdx.x * MT;

    const int te = tid & 15;
    const int tr = tid >> 4;

    float acc[4][4];
#pragma unroll
    for (int i = 0; i < 4; i++)
#pragma unroll
        for (int j = 0; j < 4; j++) acc[i][j] = 0.f;

    // global->smem loader mapping (4 threads per row / per expert, 64B each)
    const int lr = tid >> 2;   // x row 0..63
    const int lq = tid & 3;    // 16-float (4 x float4) sub-chunk
    const int we = tid >> 2;   // W expert 0..63
    const int wq = tid & 3;

    const float* xgbase = x + (size_t)(row0 + lr) * HDIM + lq * 16;
    const float* wgbase = W + (size_t)we * HDIM + wq * 16;

    for (int k0 = 0; k0 < HDIM; k0 += KC) {
        // prefetch into registers before the barrier
        const float4* xg = (const float4*)(xgbase + k0);
        float4 a0 = xg[0], a1 = xg[1], a2 = xg[2], a3 = xg[3];
        const float4* wg = (const float4*)(wgbase + k0);
        float4 b0 = wg[0], b1 = wg[1], b2 = wg[2], b3 = wg[3];

        __syncthreads();   // previous chunk fully consumed

        *(float4*)&xs[lr][lq * 16 + 0]  = a0;
        *(float4*)&xs[lr][lq * 16 + 4]  = a1;
        *(float4*)&xs[lr][lq * 16 + 8]  = a2;
        *(float4*)&xs[lr][lq * 16 + 12] = a3;

        // store W transposed (scalar stores; tiny vs compute)
        const int kb = wq * 16;
        ws[kb + 0][we] = b0.x;  ws[kb + 1][we] = b0.y;
        ws[kb + 2][we] = b0.z;  ws[kb + 3][we] = b0.w;
        ws[kb + 4][we] = b1.x;  ws[kb + 5][we] = b1.y;
        ws[kb + 6][we] = b1.z;  ws[kb + 7][we] = b1.w;
        ws[kb + 8][we] = b2.x;  ws[kb + 9][we] = b2.y;
        ws[kb + 10][we] = b2.z; ws[kb + 11][we] = b2.w;
        ws[kb + 12][we] = b3.x; ws[kb + 13][we] = b3.y;
        ws[kb + 14][we] = b3.z; ws[kb + 15][we] = b3.w;

        __syncthreads();

#pragma unroll 8
        for (int k = 0; k < KC; k++) {
            float4 w4 = *(const float4*)&ws[k][te * 4];
            float x0 = xs[tr * 4 + 0][k];
            float x1 = xs[tr * 4 + 1][k];
            float x2 = xs[tr * 4 + 2][k];
            float x3 = xs[tr * 4 + 3][k];
            acc[0][0] = fmaf(x0, w4.x, acc[0][0]);
            acc[0][1] = fmaf(x0, w4.y, acc[0][1]);
            acc[0][2] = fmaf(x0, w4.z, acc[0][2]);
            acc[0][3] = fmaf(x0, w4.w, acc[0][3]);
            acc[1][0] = fmaf(x1, w4.x, acc[1][0]);
            acc[1][1] = fmaf(x1, w4.y, acc[1][1]);
            acc[1][2] = fmaf(x1, w4.z, acc[1][2]);
            acc[1][3] = fmaf(x1, w4.w, acc[1][3]);
            acc[2][0] = fmaf(x2, w4.x, acc[2][0]);
            acc[2][1] = fmaf(x2, w4.y, acc[2][1]);
            acc[2][2] = fmaf(x2, w4.z, acc[2][2]);
            acc[2][3] = fmaf(x2, w4.w, acc[2][3]);
            acc[3][0] = fmaf(x3, w4.x, acc[3][0]);
            acc[3][1] = fmaf(x3, w4.y, acc[3][1]);
            acc[3][2] = fmaf(x3, w4.z, acc[3][2]);
            acc[3][3] = fmaf(x3, w4.w, acc[3][3]);
        }
    }

    __syncthreads();   // everyone done reading xs -> reuse as logits buffer

    // logits[row][e], stride 68 to stay conflict-light for row-major scans
#pragma unroll
    for (int i = 0; i < 4; i++)
#pragma unroll
        for (int j = 0; j < 4; j++)
            xs[tr * 4 + i][te * 4 + j] = acc[i][j];

    __syncthreads();

    // one thread per row: softmax + top-2 + p1 normalization
    if (tid < MT) {
        const int row = row0 + tid;
        float mx = -INFINITY;
#pragma unroll 8
        for (int e = 0; e < NEXP; e++) mx = fmaxf(mx, xs[tid][e]);

        float sum = 0.f;
#pragma unroll 8
        for (int e = 0; e < NEXP; e++) sum += expf(xs[tid][e] - mx);
        const float inv = 1.f / sum;

        // top-2 on logits (softmax is monotone); strict '>' keeps the
        // lowest index on ties, matching lax.top_k.
        float v1 = -INFINITY, v2 = -INFINITY;
        int i1 = 0, i2 = 0;
        for (int e = 0; e < NEXP; e++) {
            float l = xs[tid][e];
            if (l > v1) { v2 = v1; i2 = i1; v1 = l; i1 = e; }
            else if (l > v2) { v2 = l; i2 = e; }
        }

        float* srow = scores + (size_t)row * NEXP;
#pragma unroll 8
        for (int e = 0; e < NEXP; e++) srow[e] = expf(xs[tid][e] - mx) * inv;

        const float p1 = expf(v1 - mx) * inv;
        const float p2 = expf(v2 - mx) * inv;
        const float ns = 1.f / (p1 + p2);
        wout[row * 2 + 0] = p1 * ns;
        wout[row * 2 + 1] = p2 * ns;
        iout[row * 2 + 0] = (float)i1;
        iout[row * 2 + 1] = (float)i2;
    }
}

extern "C" void kernel_launch(void* const* d_in, const int* in_sizes, int n_in,
                              void* d_out, int out_size)
{
    const float* x = (const float*)d_in[0];
    const float* W = (const float*)d_in[1];
    // d_in[2] = top_k (always 2 for this problem shape)

    float* out    = (float*)d_out;
    float* scores = out;                                   // [N, E]
    float* wout   = out + (size_t)NROWS * NEXP;            // [N, 2]
    float* iout   = wout + (size_t)NROWS * TOPK;           // [N, 2] (value-cast indices)

    router_kernel<<<NROWS / MT, NTHR>>>(x, W, scores, wout, iout);
}

// round 8
// speedup vs baseline: 1.6224x; 1.6224x over previous
#include <cuda_runtime.h>
#include <cuda_bf16.h>
#include <cstdint>
#include <math.h>

#define NROWS 16384
#define HDIM  4096
#define NEXP  64
#define KC    32
#define NCHUNK (HDIM / KC)      // 128
#define TM    128               // rows per block
#define NTHR  128               // 4 warps
#define NBLK  (NROWS / TM)      // 128 blocks, single wave

#define APITCH  80              // bytes per smem row (32 bf16 + pad) — conflict-free ldmatrix
#define A_SPLIT (TM * APITCH)   // 10240 B per A split
#define B_SPLIT (NEXP * APITCH) // 5120 B per B split
#define SM_B0   (2 * A_SPLIT)   // 20480
#define LPITCH  65              // logits smem pitch (floats): bank-conflict-free column reads
#define SM_TOTAL 35840          // max(GEMM 30720, logits 128*65*4=33280)

// Pre-split W: 2 bf16 terms (round-to-nearest), [split][e*HDIM + k]. 1 MB.
__device__ __nv_bfloat16 g_ws[2][NEXP * HDIM];

__device__ __forceinline__ uint32_t smem_u32(const void* p) {
    uint32_t a;
    asm("{ .reg .u64 t; cvta.to.shared.u64 t, %1; cvt.u32.u64 %0, t; }" : "=r"(a) : "l"(p));
    return a;
}
__device__ __forceinline__ void ldsm4(uint32_t* r, uint32_t addr) {
    asm volatile("ldmatrix.sync.aligned.m8n8.x4.shared.b16 {%0,%1,%2,%3}, [%4];"
                 : "=r"(r[0]), "=r"(r[1]), "=r"(r[2]), "=r"(r[3]) : "r"(addr));
}
__device__ __forceinline__ void mma16816(float* c, const uint32_t* a, const uint32_t* b) {
    asm volatile("mma.sync.aligned.m16n8k16.row.col.f32.bf16.bf16.f32 "
                 "{%0,%1,%2,%3}, {%4,%5,%6,%7}, {%8,%9}, {%0,%1,%2,%3};"
                 : "+f"(c[0]), "+f"(c[1]), "+f"(c[2]), "+f"(c[3])
                 : "r"(a[0]), "r"(a[1]), "r"(a[2]), "r"(a[3]), "r"(b[0]), "r"(b[1]));
}
// pack two fp32 -> bf16x2 (lo = f0), and return bf16-exact fp32 values for residual
__device__ __forceinline__ uint32_t pack_rn(float f0, float f1) {
    uint32_t r;
    asm("cvt.rn.bf16x2.f32 %0, %1, %2;" : "=r"(r) : "f"(f1), "f"(f0));
    return r;
}

__global__ void split_w_kernel(const float* __restrict__ W) {
    int idx = blockIdx.x * 256 + threadIdx.x;
    if (idx >= NEXP * HDIM) return;
    float v = W[idx];
    __nv_bfloat16 h1 = __float2bfloat16(v);               // round-to-nearest
    float r = v - __bfloat162float(h1);                    // exact
    g_ws[0][idx] = h1;
    g_ws[1][idx] = __float2bfloat16(r);
}

__global__ void __launch_bounds__(NTHR, 1)
router_hmma(const float* __restrict__ x,
            float* __restrict__ scores, float* __restrict__ wout,
            float* __restrict__ iout)
{
    __shared__ __align__(16) char sm[SM_TOTAL];
    const uint32_t smb = smem_u32(sm);

    const int tid = threadIdx.x;
    const int w   = tid >> 5;
    const int l   = tid & 31;
    const int row = blockIdx.x * TM + tid;     // one x-row per thread (load/epilogue)
    const float* xrow = x + (size_t)row * HDIM;

    float acc[2][8][4];
#pragma unroll
    for (int t = 0; t < 2; t++)
#pragma unroll
        for (int n = 0; n < 8; n++)
#pragma unroll
            for (int i = 0; i < 4; i++) acc[t][n][i] = 0.f;

    // ldmatrix lane-address bases (A: rows of m, k-halves; B: rows of n, k-halves)
    const uint32_t a_base = smb + (uint32_t)((w * 32 + (l & 15)) * APITCH + (l >> 4) * 16);
    const uint32_t b_base = smb + SM_B0 +
        (uint32_t)((((l & 7) + ((l >> 4) & 1) * 8)) * APITCH + ((l >> 3) & 1) * 16);

    // B loader mapping: 4 x 16B per thread per chunk (2 splits x 64 exp x 64B)
    const __nv_bfloat16* bsrc[4];
    uint32_t bdst[4];
#pragma unroll
    for (int p = 0; p < 4; p++) {
        int idx = tid + p * NTHR;      // 0..511
        int sp  = idx >> 8;
        int rem = idx & 255;
        int q   = rem >> 6;            // 16B sub-chunk within the 64B row
        int e   = rem & 63;            // expert (q-major outer => conflict-free stores)
        bsrc[p] = &g_ws[sp][(size_t)e * HDIM + q * 8];
        bdst[p] = (uint32_t)(sp * B_SPLIT + e * APITCH + q * 16);
    }

    // prefetch chunk 0
    float4 xv[8];
    uint4  bv[4];
#pragma unroll
    for (int j = 0; j < 8; j++) xv[j] = ((const float4*)xrow)[j];
#pragma unroll
    for (int p = 0; p < 4; p++) bv[p] = *(const uint4*)bsrc[p];

    for (int c = 0; c < NCHUNK; c++) {
        __syncthreads();               // previous chunk fully consumed

        // ---- A: split 32 fp32 -> 2x16 bf16x2, store both splits (this thread's row) ----
        {
            uint32_t p1[16], p2[16];
            const float* xf = (const float*)xv;
#pragma unroll
            for (int j = 0; j < 16; j++) {
                float f0 = xf[2 * j], f1 = xf[2 * j + 1];
                uint32_t hi = pack_rn(f0, f1);
                float g0 = __uint_as_float(hi << 16);
                float g1 = __uint_as_float(hi & 0xFFFF0000u);
                p1[j] = hi;
                p2[j] = pack_rn(f0 - g0, f1 - g1);
            }
            char* sA = sm + tid * APITCH;
#pragma unroll
            for (int j = 0; j < 4; j++) {
                *(uint4*)(sA + j * 16)           = ((uint4*)p1)[j];
                *(uint4*)(sA + A_SPLIT + j * 16) = ((uint4*)p2)[j];
            }
        }
        // ---- B: store pre-split W tile ----
#pragma unroll
        for (int p = 0; p < 4; p++)
            *(uint4*)(sm + SM_B0 + bdst[p]) = bv[p];

        __syncthreads();

        // prefetch next chunk while MMAs run
        if (c + 1 < NCHUNK) {
            const float4* xg = (const float4*)(xrow + (size_t)(c + 1) * KC);
#pragma unroll
            for (int j = 0; j < 8; j++) xv[j] = xg[j];
#pragma unroll
            for (int p = 0; p < 4; p++) bv[p] = *(const uint4*)(bsrc[p] + (size_t)(c + 1) * KC);
        }

        // ---- MMA: 2 k16-steps x (3 split-products x 16 tiles) ----
#pragma unroll
        for (int ks = 0; ks < 2; ks++) {
            uint32_t A0[8], A1[8];
            ldsm4(A0,     a_base + ks * 32);
            ldsm4(A0 + 4, a_base + 1280 + ks * 32);              // t=1: +16*80
            ldsm4(A1,     a_base + A_SPLIT + ks * 32);
            ldsm4(A1 + 4, a_base + A_SPLIT + 1280 + ks * 32);
            uint32_t B0[16], B1[16];
#pragma unroll
            for (int q = 0; q < 4; q++) {
                ldsm4(B0 + q * 4, b_base + q * 1280 + ks * 32);  // frags: n-tiles 2q, 2q+1
                ldsm4(B1 + q * 4, b_base + B_SPLIT + q * 1280 + ks * 32);
            }
#pragma unroll
            for (int t = 0; t < 2; t++)
#pragma unroll
                for (int n = 0; n < 8; n++) {
                    mma16816(acc[t][n], A0 + t * 4, B0 + n * 2);   // a1*b1
                    mma16816(acc[t][n], A0 + t * 4, B1 + n * 2);   // a1*b2
                    mma16816(acc[t][n], A1 + t * 4, B0 + n * 2);   // a2*b1
                }
        }
    }

    // ---- scatter accumulators (logits) to smem ----
    __syncthreads();
    float* ls = (float*)sm;
#pragma unroll
    for (int t = 0; t < 2; t++)
#pragma unroll
        for (int n = 0; n < 8; n++)
#pragma unroll
            for (int i = 0; i < 4; i++) {
                int r = w * 32 + t * 16 + (l >> 2) + (i >> 1) * 8;
                int cc = n * 8 + (l & 3) * 2 + (i & 1);
                ls[r * LPITCH + cc] = acc[t][n][i];
            }
    __syncthreads();

    // ---- per-row softmax + top-2 + p1 norm (thread tid owns row tid) ----
    {
        float d[64];
#pragma unroll
        for (int e = 0; e < 64; e++) d[e] = ls[tid * LPITCH + e];

        float mx = d[0];
#pragma unroll
        for (int e = 1; e < 64; e++) mx = fmaxf(mx, d[e]);
        float sum = 0.f;
#pragma unroll
        for (int e = 0; e < 64; e++) sum += expf(d[e] - mx);
        const float inv = 1.f / sum;

        float v1 = -INFINITY, v2 = -INFINITY; int i1 = 0, i2 = 0;
#pragma unroll
        for (int e = 0; e < 64; e++) {
            float lg = d[e];
            if (lg > v1)      { v2 = v1; i2 = i1; v1 = lg; i1 = e; }
            else if (lg > v2) { v2 = lg; i2 = e; }
        }

        float* srow = scores + (size_t)row * NEXP;
#pragma unroll
        for (int q = 0; q < 16; q++) {
            float4 o;
            o.x = expf(d[4 * q + 0] - mx) * inv;
            o.y = expf(d[4 * q + 1] - mx) * inv;
            o.z = expf(d[4 * q + 2] - mx) * inv;
            o.w = expf(d[4 * q + 3] - mx) * inv;
            ((float4*)srow)[q] = o;
        }

        const float p1 = expf(v1 - mx) * inv;
        const float p2 = expf(v2 - mx) * inv;
        const float ns = 1.f / (p1 + p2);
        wout[row * 2 + 0] = p1 * ns;
        wout[row * 2 + 1] = p2 * ns;
        iout[row * 2 + 0] = (float)i1;
        iout[row * 2 + 1] = (float)i2;
    }
}

extern "C" void kernel_launch(void* const* d_in, const int* in_sizes, int n_in,
                              void* d_out, int out_size)
{
    const float* x = (const float*)d_in[0];
    const float* W = (const float*)d_in[1];

    float* out    = (float*)d_out;
    float* scores = out;                          // [N, E]
    float* wout   = out + (size_t)NROWS * NEXP;   // [N, 2]
    float* iout   = wout + (size_t)NROWS * 2;     // [N, 2] (value-cast indices)

    split_w_kernel<<<(NEXP * HDIM + 255) / 256, 256>>>(W);
    router_hmma<<<NBLK, NTHR>>>(x, scores, wout, iout);
}

// round 9
// speedup vs baseline: 1.9936x; 1.2288x over previous
#include <cuda_runtime.h>
#include <cuda_bf16.h>
#include <cstdint>
#include <math.h>

#define NROWS 16384
#define HDIM  4096
#define NEXP  64
#define KC    32
#define NCHUNK (HDIM / KC)      // 128
#define TM    128               // rows per block
#define NTHR  256               // 8 warps
#define NBLK  (NROWS / TM)      // 128 blocks, single wave

#define APITCH  80              // bytes per smem row (32 bf16 + pad) — conflict-free ldmatrix
#define A_SPLIT (TM * APITCH)   // 10240 B per A split
#define B_SPLIT (NEXP * APITCH) // 5120 B per B split
#define SM_B0   (2 * A_SPLIT)   // 20480
#define LPITCH  65              // logits smem pitch (floats)
#define SM_TOTAL 35840          // max(GEMM 30720, logits 128*65*4=33280)

// Pre-split W: 2 bf16 terms (round-to-nearest), [split][e*HDIM + k]. 1 MB.
__device__ __nv_bfloat16 g_ws[2][NEXP * HDIM];

__device__ __forceinline__ uint32_t smem_u32(const void* p) {
    uint32_t a;
    asm("{ .reg .u64 t; cvta.to.shared.u64 t, %1; cvt.u32.u64 %0, t; }" : "=r"(a) : "l"(p));
    return a;
}
__device__ __forceinline__ void ldsm4(uint32_t* r, uint32_t addr) {
    asm volatile("ldmatrix.sync.aligned.m8n8.x4.shared.b16 {%0,%1,%2,%3}, [%4];"
                 : "=r"(r[0]), "=r"(r[1]), "=r"(r[2]), "=r"(r[3]) : "r"(addr));
}
__device__ __forceinline__ void mma16816(float* c, const uint32_t* a, const uint32_t* b) {
    asm volatile("mma.sync.aligned.m16n8k16.row.col.f32.bf16.bf16.f32 "
                 "{%0,%1,%2,%3}, {%4,%5,%6,%7}, {%8,%9}, {%0,%1,%2,%3};"
                 : "+f"(c[0]), "+f"(c[1]), "+f"(c[2]), "+f"(c[3])
                 : "r"(a[0]), "r"(a[1]), "r"(a[2]), "r"(a[3]), "r"(b[0]), "r"(b[1]));
}
__device__ __forceinline__ uint32_t pack_rn(float f0, float f1) {
    uint32_t r;
    asm("cvt.rn.bf16x2.f32 %0, %1, %2;" : "=r"(r) : "f"(f1), "f"(f0));
    return r;
}

__global__ void split_w_kernel(const float* __restrict__ W) {
    int idx = blockIdx.x * 256 + threadIdx.x;
    if (idx >= NEXP * HDIM) return;
    float v = W[idx];
    __nv_bfloat16 h1 = __float2bfloat16(v);               // round-to-nearest
    float r = v - __bfloat162float(h1);                    // exact residual
    g_ws[0][idx] = h1;
    g_ws[1][idx] = __float2bfloat16(r);
}

__global__ void __launch_bounds__(NTHR, 1)
router_hmma(const float* __restrict__ x,
            float* __restrict__ scores, float* __restrict__ wout,
            float* __restrict__ iout)
{
    __shared__ __align__(16) char sm[SM_TOTAL];
    const uint32_t smb = smem_u32(sm);

    const int tid = threadIdx.x;
    const int w   = tid >> 5;
    const int l   = tid & 31;
    const int mt  = w & 3;          // m-tile group: rows mt*32 .. mt*32+31
    const int nh  = w >> 2;         // n-half: experts nh*32 .. nh*32+31
    const int row0 = blockIdx.x * TM;

    // A-loader: 2 threads per row, 16 floats each
    const int ldr  = tid >> 1;      // row 0..127
    const int half = tid & 1;       // k-half of the 32-chunk
    const float* xld = x + (size_t)(row0 + ldr) * HDIM + half * 16;

    float acc[2][4][4];
#pragma unroll
    for (int t = 0; t < 2; t++)
#pragma unroll
        for (int n = 0; n < 4; n++)
#pragma unroll
            for (int i = 0; i < 4; i++) acc[t][n][i] = 0.f;

    // ldmatrix lane-address bases
    const uint32_t a_base = smb + (uint32_t)((mt * 32 + (l & 15)) * APITCH + (l >> 4) * 16);
    const uint32_t b_base = smb + SM_B0 +
        (uint32_t)((nh * 32 + (l & 7) + ((l >> 4) & 1) * 8) * APITCH + ((l >> 3) & 1) * 16);

    // B loader mapping: 2 x 16B per thread per chunk (2 splits x 64 exp x 64B)
    const __nv_bfloat16* bsrc[2];
    uint32_t bdst[2];
#pragma unroll
    for (int p = 0; p < 2; p++) {
        int idx = tid + p * NTHR;      // 0..511
        int sp  = idx >> 8;
        int rem = idx & 255;
        int q   = rem >> 6;            // 16B sub-chunk within the 64B row
        int e   = rem & 63;            // expert
        bsrc[p] = &g_ws[sp][(size_t)e * HDIM + q * 8];
        bdst[p] = (uint32_t)(sp * B_SPLIT + e * APITCH + q * 16);
    }

    // prefetch chunk 0
    float4 xv[4];
    uint4  bv[2];
#pragma unroll
    for (int j = 0; j < 4; j++) xv[j] = ((const float4*)xld)[j];
#pragma unroll
    for (int p = 0; p < 2; p++) bv[p] = *(const uint4*)bsrc[p];

    for (int c = 0; c < NCHUNK; c++) {
        __syncthreads();               // previous chunk fully consumed

        // ---- A: split 16 fp32 -> 2x8 bf16x2, store both splits ----
        {
            uint32_t p1[8], p2[8];
            const float* xf = (const float*)xv;
#pragma unroll
            for (int j = 0; j < 8; j++) {
                float f0 = xf[2 * j], f1 = xf[2 * j + 1];
                uint32_t hi = pack_rn(f0, f1);
                float g0 = __uint_as_float(hi << 16);
                float g1 = __uint_as_float(hi & 0xFFFF0000u);
                p1[j] = hi;
                p2[j] = pack_rn(f0 - g0, f1 - g1);
            }
            char* sA = sm + ldr * APITCH + half * 32;
            *(uint4*)(sA + 0)             = ((uint4*)p1)[0];
            *(uint4*)(sA + 16)            = ((uint4*)p1)[1];
            *(uint4*)(sA + A_SPLIT + 0)   = ((uint4*)p2)[0];
            *(uint4*)(sA + A_SPLIT + 16)  = ((uint4*)p2)[1];
        }
        // ---- B: store pre-split W tile ----
#pragma unroll
        for (int p = 0; p < 2; p++)
            *(uint4*)(sm + SM_B0 + bdst[p]) = bv[p];

        __syncthreads();

        // prefetch next chunk while MMAs run
        if (c + 1 < NCHUNK) {
            const float4* xg = (const float4*)(xld + (size_t)(c + 1) * KC);
#pragma unroll
            for (int j = 0; j < 4; j++) xv[j] = xg[j];
#pragma unroll
            for (int p = 0; p < 2; p++) bv[p] = *(const uint4*)(bsrc[p] + (size_t)(c + 1) * KC);
        }

        // ---- MMA: 2 k16-steps x (2 m-tiles x 4 n-tiles x 3 split-products) ----
#pragma unroll
        for (int ks = 0; ks < 2; ks++) {
            uint32_t A0[8], A1[8];
            ldsm4(A0,     a_base + ks * 32);
            ldsm4(A0 + 4, a_base + 1280 + ks * 32);              // t=1: +16*80
            ldsm4(A1,     a_base + A_SPLIT + ks * 32);
            ldsm4(A1 + 4, a_base + A_SPLIT + 1280 + ks * 32);
            uint32_t B0[8], B1[8];
#pragma unroll
            for (int q = 0; q < 2; q++) {
                ldsm4(B0 + q * 4, b_base + q * 1280 + ks * 32);  // n-tiles 2q, 2q+1
                ldsm4(B1 + q * 4, b_base + B_SPLIT + q * 1280 + ks * 32);
            }
#pragma unroll
            for (int t = 0; t < 2; t++)
#pragma unroll
                for (int n = 0; n < 4; n++) {
                    mma16816(acc[t][n], A0 + t * 4, B0 + n * 2);   // a1*b1
                    mma16816(acc[t][n], A0 + t * 4, B1 + n * 2);   // a1*b2
                    mma16816(acc[t][n], A1 + t * 4, B0 + n * 2);   // a2*b1
                }
        }
    }

    // ---- scatter accumulators (logits) to smem ----
    __syncthreads();
    float* ls = (float*)sm;
#pragma unroll
    for (int t = 0; t < 2; t++)
#pragma unroll
        for (int n = 0; n < 4; n++)
#pragma unroll
            for (int i = 0; i < 4; i++) {
                int r  = mt * 32 + t * 16 + (l >> 2) + (i >> 1) * 8;
                int cc = nh * 32 + n * 8 + (l & 3) * 2 + (i & 1);
                ls[r * LPITCH + cc] = acc[t][n][i];
            }
    __syncthreads();

    // ---- per-row softmax + top-2 + p1 norm (threads 0..127 own rows) ----
    if (tid < TM) {
        const int row = row0 + tid;
        float d[64];
#pragma unroll
        for (int e = 0; e < 64; e++) d[e] = ls[tid * LPITCH + e];

        float mx = d[0];
#pragma unroll
        for (int e = 1; e < 64; e++) mx = fmaxf(mx, d[e]);
        float sum = 0.f;
#pragma unroll
        for (int e = 0; e < 64; e++) sum += expf(d[e] - mx);
        const float inv = 1.f / sum;

        float v1 = -INFINITY, v2 = -INFINITY; int i1 = 0, i2 = 0;
#pragma unroll
        for (int e = 0; e < 64; e++) {
            float lg = d[e];
            if (lg > v1)      { v2 = v1; i2 = i1; v1 = lg; i1 = e; }
            else if (lg > v2) { v2 = lg; i2 = e; }
        }

        float* srow = scores + (size_t)row * NEXP;
#pragma unroll
        for (int q = 0; q < 16; q++) {
            float4 o;
            o.x = expf(d[4 * q + 0] - mx) * inv;
            o.y = expf(d[4 * q + 1] - mx) * inv;
            o.z = expf(d[4 * q + 2] - mx) * inv;
            o.w = expf(d[4 * q + 3] - mx) * inv;
            ((float4*)srow)[q] = o;
        }

        const float p1 = expf(v1 - mx) * inv;
        const float p2 = expf(v2 - mx) * inv;
        const float ns = 1.f / (p1 + p2);
        wout[row * 2 + 0] = p1 * ns;
        wout[row * 2 + 1] = p2 * ns;
        iout[row * 2 + 0] = (float)i1;
        iout[row * 2 + 1] = (float)i2;
    }
}

extern "C" void kernel_launch(void* const* d_in, const int* in_sizes, int n_in,
                              void* d_out, int out_size)
{
    const float* x = (const float*)d_in[0];
    const float* W = (const float*)d_in[1];

    float* out    = (float*)d_out;
    float* scores = out;                          // [N, E]
    float* wout   = out + (size_t)NROWS * NEXP;   // [N, 2]
    float* iout   = wout + (size_t)NROWS * 2;     // [N, 2] (value-cast indices)

    split_w_kernel<<<(NEXP * HDIM + 255) / 256, 256>>>(W);
    router_hmma<<<NBLK, NTHR>>>(x, scores, wout, iout);
}

// round 10
// speedup vs baseline: 2.1319x; 1.0693x over previous
#include <cuda_runtime.h>
#include <cuda_bf16.h>
#include <cstdint>
#include <math.h>

#define NROWS 16384
#define HDIM  4096
#define NEXP  64
#define KC    64
#define NCHUNK (HDIM / KC)      // 64
#define TM    128               // rows per block
#define NTHR  256               // 8 warps
#define NBLK  (NROWS / TM)      // 128 blocks, single wave

#define APITCH  144             // bytes per smem row (64 bf16 + 16B pad) — conflict-free ldmatrix
#define A_SPLIT (TM * APITCH)   // 18432 B per A split
#define B_SPLIT (NEXP * APITCH) // 9216 B per B split
#define SM_B0   (2 * A_SPLIT)   // 36864 (B region within one buffer)
#define BUF_BYTES (2 * A_SPLIT + 2 * B_SPLIT)   // 55296 per stage
#define SM_TOTAL (2 * BUF_BYTES)                 // 110592 (logits 33280 reuses buf0)
#define LPITCH  65              // logits smem pitch (floats)

// Pre-split W: 2 bf16 terms (round-to-nearest), [split][e*HDIM + k]. 1 MB.
__device__ __nv_bfloat16 g_ws[2][NEXP * HDIM];

__device__ __forceinline__ uint32_t smem_u32(const void* p) {
    uint32_t a;
    asm("{ .reg .u64 t; cvta.to.shared.u64 t, %1; cvt.u32.u64 %0, t; }" : "=r"(a) : "l"(p));
    return a;
}
__device__ __forceinline__ void ldsm4(uint32_t* r, uint32_t addr) {
    asm volatile("ldmatrix.sync.aligned.m8n8.x4.shared.b16 {%0,%1,%2,%3}, [%4];"
                 : "=r"(r[0]), "=r"(r[1]), "=r"(r[2]), "=r"(r[3]) : "r"(addr));
}
__device__ __forceinline__ void mma16816(float* c, const uint32_t* a, const uint32_t* b) {
    asm volatile("mma.sync.aligned.m16n8k16.row.col.f32.bf16.bf16.f32 "
                 "{%0,%1,%2,%3}, {%4,%5,%6,%7}, {%8,%9}, {%0,%1,%2,%3};"
                 : "+f"(c[0]), "+f"(c[1]), "+f"(c[2]), "+f"(c[3])
                 : "r"(a[0]), "r"(a[1]), "r"(a[2]), "r"(a[3]), "r"(b[0]), "r"(b[1]));
}
__device__ __forceinline__ uint32_t pack_rn(float f0, float f1) {
    uint32_t r;
    asm("cvt.rn.bf16x2.f32 %0, %1, %2;" : "=r"(r) : "f"(f1), "f"(f0));
    return r;
}

__global__ void split_w_kernel(const float* __restrict__ W) {
    int idx = blockIdx.x * 256 + threadIdx.x;
    if (idx >= NEXP * HDIM) return;
    float v = W[idx];
    __nv_bfloat16 h1 = __float2bfloat16(v);               // round-to-nearest
    float r = v - __bfloat162float(h1);                    // exact residual
    g_ws[0][idx] = h1;
    g_ws[1][idx] = __float2bfloat16(r);
}

__global__ void __launch_bounds__(NTHR, 1)
router_hmma(const float* __restrict__ x,
            float* __restrict__ scores, float* __restrict__ wout,
            float* __restrict__ iout)
{
    extern __shared__ __align__(16) char sm[];
    const uint32_t smb = smem_u32(sm);

    const int tid = threadIdx.x;
    const int l   = tid & 31;
    const int w   = tid >> 5;
    const int mt  = w & 3;          // m-tile group: rows mt*32 .. +31
    const int nh  = w >> 2;         // n-half: experts nh*32 .. +31
    const int row0 = blockIdx.x * TM;

    // A-loader: 2 threads per row, 32 floats (128B) each
    const int ldr  = tid >> 1;
    const int half = tid & 1;
    const float* xld = x + (size_t)(row0 + ldr) * HDIM + half * 32;

    float acc[2][4][4];
#pragma unroll
    for (int t = 0; t < 2; t++)
#pragma unroll
        for (int n = 0; n < 4; n++)
#pragma unroll
            for (int i = 0; i < 4; i++) acc[t][n][i] = 0.f;

    // ldmatrix lane-address bases (relative to buffer start)
    const uint32_t a_rel = (uint32_t)((mt * 32 + (l & 15)) * APITCH + (l >> 4) * 16);
    const uint32_t b_rel = (uint32_t)(SM_B0 +
        (nh * 32 + (l & 7) + ((l >> 4) & 1) * 8) * APITCH + ((l >> 3) & 1) * 16);

    // B loader: 4 x 16B per thread per chunk (2 splits x 64 exp x 128B)
    const __nv_bfloat16* bsrc[4];
    uint32_t bdst[4];
#pragma unroll
    for (int p = 0; p < 4; p++) {
        int idx = tid + p * NTHR;      // 0..1023
        int sp  = idx >> 9;
        int rem = idx & 511;
        int q   = rem >> 6;            // 16B sub-chunk (0..7)
        int e   = rem & 63;
        bsrc[p] = &g_ws[sp][(size_t)e * HDIM + q * 8];
        bdst[p] = (uint32_t)(SM_B0 + sp * B_SPLIT + e * APITCH + q * 16);
    }

    float4 xv[8];
    uint4  bv[4];

    // ---- prologue: chunk 0 -> buf0; prefetch chunk 1 regs ----
#pragma unroll
    for (int j = 0; j < 8; j++) xv[j] = ((const float4*)xld)[j];
#pragma unroll
    for (int p = 0; p < 4; p++) bv[p] = *(const uint4*)bsrc[p];
    {
        uint32_t p1[16], p2[16];
        const float* xf = (const float*)xv;
#pragma unroll
        for (int j = 0; j < 16; j++) {
            float f0 = xf[2 * j], f1 = xf[2 * j + 1];
            uint32_t hi = pack_rn(f0, f1);
            p1[j] = hi;
            p2[j] = pack_rn(f0 - __uint_as_float(hi << 16),
                            f1 - __uint_as_float(hi & 0xFFFF0000u));
        }
        char* sA = sm + ldr * APITCH + half * 64;
#pragma unroll
        for (int j = 0; j < 4; j++) {
            *(uint4*)(sA + j * 16)           = ((uint4*)p1)[j];
            *(uint4*)(sA + A_SPLIT + j * 16) = ((uint4*)p2)[j];
        }
#pragma unroll
        for (int p = 0; p < 4; p++) *(uint4*)(sm + bdst[p]) = bv[p];
    }
#pragma unroll
    for (int j = 0; j < 8; j++) xv[j] = ((const float4*)(xld + KC))[j];
#pragma unroll
    for (int p = 0; p < 4; p++) bv[p] = *(const uint4*)(bsrc[p] + KC);
    __syncthreads();

    for (int c = 0; c < NCHUNK; c++) {
        const uint32_t bufb = smb + (uint32_t)((c & 1) * BUF_BYTES);
        char* nbuf = sm + ((c + 1) & 1) * BUF_BYTES;

        // ---- ks0: frags + MMA (data ready now — feed tensor pipe first) ----
#pragma unroll
        for (int ks = 0; ks < 4; ks++) {
            uint32_t A0[8], A1[8], B0[8], B1[8];
            ldsm4(A0,     bufb + a_rel + ks * 32);
            ldsm4(A0 + 4, bufb + a_rel + 2304 + ks * 32);            // +16 rows
            ldsm4(A1,     bufb + A_SPLIT + a_rel + ks * 32);
            ldsm4(A1 + 4, bufb + A_SPLIT + a_rel + 2304 + ks * 32);
            ldsm4(B0,     bufb + b_rel + ks * 32);
            ldsm4(B0 + 4, bufb + b_rel + 2304 + ks * 32);
            ldsm4(B1,     bufb + B_SPLIT + b_rel + ks * 32);
            ldsm4(B1 + 4, bufb + B_SPLIT + b_rel + 2304 + ks * 32);

            // product-outer order: 8 independent accumulators between reuses
#pragma unroll
            for (int t = 0; t < 2; t++)
#pragma unroll
                for (int n = 0; n < 4; n++) mma16816(acc[t][n], A0 + t * 4, B0 + n * 2);
#pragma unroll
            for (int t = 0; t < 2; t++)
#pragma unroll
                for (int n = 0; n < 4; n++) mma16816(acc[t][n], A0 + t * 4, B1 + n * 2);
#pragma unroll
            for (int t = 0; t < 2; t++)
#pragma unroll
                for (int n = 0; n < 4; n++) mma16816(acc[t][n], A1 + t * 4, B0 + n * 2);

            if (ks == 0) {
                // ---- convert + store chunk c+1 into the other buffer ----
                if (c + 1 < NCHUNK) {
                    uint32_t p1[16], p2[16];
                    const float* xf = (const float*)xv;
#pragma unroll
                    for (int j = 0; j < 16; j++) {
                        float f0 = xf[2 * j], f1 = xf[2 * j + 1];
                        uint32_t hi = pack_rn(f0, f1);
                        p1[j] = hi;
                        p2[j] = pack_rn(f0 - __uint_as_float(hi << 16),
                                        f1 - __uint_as_float(hi & 0xFFFF0000u));
                    }
                    char* sA = nbuf + ldr * APITCH + half * 64;
#pragma unroll
                    for (int j = 0; j < 4; j++) {
                        *(uint4*)(sA + j * 16)           = ((uint4*)p1)[j];
                        *(uint4*)(sA + A_SPLIT + j * 16) = ((uint4*)p2)[j];
                    }
#pragma unroll
                    for (int p = 0; p < 4; p++) *(uint4*)(nbuf + bdst[p]) = bv[p];
                }
                // ---- prefetch chunk c+2 ----
                if (c + 2 < NCHUNK) {
                    const float4* xg = (const float4*)(xld + (size_t)(c + 2) * KC);
#pragma unroll
                    for (int j = 0; j < 8; j++) xv[j] = xg[j];
#pragma unroll
                    for (int p = 0; p < 4; p++)
                        bv[p] = *(const uint4*)(bsrc[p] + (size_t)(c + 2) * KC);
                }
            }
        }
        __syncthreads();   // stores for c+1 visible; all ldsm of c done
    }

    // ---- scatter accumulators (logits) to smem (buf0 region) ----
    float* ls = (float*)sm;
#pragma unroll
    for (int t = 0; t < 2; t++)
#pragma unroll
        for (int n = 0; n < 4; n++)
#pragma unroll
            for (int i = 0; i < 4; i++) {
                int r  = mt * 32 + t * 16 + (l >> 2) + (i >> 1) * 8;
                int cc = nh * 32 + n * 8 + (l & 3) * 2 + (i & 1);
                ls[r * LPITCH + cc] = acc[t][n][i];
            }
    __syncthreads();

    // ---- per-row softmax + top-2 + p1 norm (threads 0..127 own rows) ----
    if (tid < TM) {
        const int row = row0 + tid;
        float d[64];
#pragma unroll
        for (int e = 0; e < 64; e++) d[e] = ls[tid * LPITCH + e];

        float mx = d[0];
#pragma unroll
        for (int e = 1; e < 64; e++) mx = fmaxf(mx, d[e]);
        float sum = 0.f;
#pragma unroll
        for (int e = 0; e < 64; e++) sum += expf(d[e] - mx);
        const float inv = 1.f / sum;

        float v1 = -INFINITY, v2 = -INFINITY; int i1 = 0, i2 = 0;
#pragma unroll
        for (int e = 0; e < 64; e++) {
            float lg = d[e];
            if (lg > v1)      { v2 = v1; i2 = i1; v1 = lg; i1 = e; }
            else if (lg > v2) { v2 = lg; i2 = e; }
        }

        float* srow = scores + (size_t)row * NEXP;
#pragma unroll
        for (int q = 0; q < 16; q++) {
            float4 o;
            o.x = expf(d[4 * q + 0] - mx) * inv;
            o.y = expf(d[4 * q + 1] - mx) * inv;
            o.z = expf(d[4 * q + 2] - mx) * inv;
            o.w = expf(d[4 * q + 3] - mx) * inv;
            ((float4*)srow)[q] = o;
        }

        const float p1 = expf(v1 - mx) * inv;
        const float p2 = expf(v2 - mx) * inv;
        const float ns = 1.f / (p1 + p2);
        wout[row * 2 + 0] = p1 * ns;
        wout[row * 2 + 1] = p2 * ns;
        iout[row * 2 + 0] = (float)i1;
        iout[row * 2 + 1] = (float)i2;
    }
}

extern "C" void kernel_launch(void* const* d_in, const int* in_sizes, int n_in,
                              void* d_out, int out_size)
{
    const float* x = (const float*)d_in[0];
    const float* W = (const float*)d_in[1];

    float* out    = (float*)d_out;
    float* scores = out;                          // [N, E]
    float* wout   = out + (size_t)NROWS * NEXP;   // [N, 2]
    float* iout   = wout + (size_t)NROWS * 2;     // [N, 2] (value-cast indices)

    cudaFuncSetAttribute(router_hmma,
                         cudaFuncAttributeMaxDynamicSharedMemorySize, SM_TOTAL);

    split_w_kernel<<<(NEXP * HDIM + 255) / 256, 256>>>(W);
    router_hmma<<<NBLK, NTHR, SM_TOTAL>>>(x, scores, wout, iout);
}

// round 11
// speedup vs baseline: 3.4338x; 1.6107x over previous
#include <cuda_runtime.h>
#include <cuda_bf16.h>
#include <cstdint>
#include <math.h>

#define NROWS 16384
#define HDIM  4096
#define NEXP  64
#define KC    64
#define NCHUNK (HDIM / KC)      // 64
#define TM    128               // rows per block
#define NTHR  256               // 8 warps
#define NBLK  (NROWS / TM)      // 128 blocks, single wave

#define APITCH  144             // bytes per smem row (64 bf16 + 16B pad)
#define A_SPLIT (TM * APITCH)   // 18432 B per A split
#define B_SPLIT (NEXP * APITCH) // 9216 B per B split
#define SM_B0   (2 * A_SPLIT)   // 36864 (B region within one buffer)
#define BUF_BYTES (2 * A_SPLIT + 2 * B_SPLIT)   // 55296 per stage
#define SM_TOTAL (2 * BUF_BYTES)                 // 110592
#define LPITCH  65              // logits smem pitch (floats)

// Pre-split W: 2 bf16 terms (round-to-nearest), [split][e*HDIM + k]. 1 MB.
__device__ __nv_bfloat16 g_ws[2][NEXP * HDIM];

__device__ __forceinline__ uint32_t smem_u32(const void* p) {
    uint32_t a;
    asm("{ .reg .u64 t; cvta.to.shared.u64 t, %1; cvt.u32.u64 %0, t; }" : "=r"(a) : "l"(p));
    return a;
}
__device__ __forceinline__ void ldsm4(uint32_t* r, uint32_t addr) {
    asm volatile("ldmatrix.sync.aligned.m8n8.x4.shared.b16 {%0,%1,%2,%3}, [%4];"
                 : "=r"(r[0]), "=r"(r[1]), "=r"(r[2]), "=r"(r[3]) : "r"(addr));
}
__device__ __forceinline__ void mma16816(float* c, const uint32_t* a, const uint32_t* b) {
    asm volatile("mma.sync.aligned.m16n8k16.row.col.f32.bf16.bf16.f32 "
                 "{%0,%1,%2,%3}, {%4,%5,%6,%7}, {%8,%9}, {%0,%1,%2,%3};"
                 : "+f"(c[0]), "+f"(c[1]), "+f"(c[2]), "+f"(c[3])
                 : "r"(a[0]), "r"(a[1]), "r"(a[2]), "r"(a[3]), "r"(b[0]), "r"(b[1]));
}
__device__ __forceinline__ uint32_t pack_rn(float f0, float f1) {
    uint32_t r;
    asm("cvt.rn.bf16x2.f32 %0, %1, %2;" : "=r"(r) : "f"(f1), "f"(f0));
    return r;
}
#define CP_ASYNC16(dst, src) \
    asm volatile("cp.async.cg.shared.global [%0], [%1], 16;" :: "r"(dst), "l"(src) : "memory")
#define CP_COMMIT() asm volatile("cp.async.commit_group;" ::: "memory")
#define CP_WAIT0()  asm volatile("cp.async.wait_group 0;" ::: "memory")

__global__ void split_w_kernel(const float* __restrict__ W) {
    int idx = blockIdx.x * 256 + threadIdx.x;
    if (idx >= NEXP * HDIM) return;
    float v = W[idx];
    __nv_bfloat16 h1 = __float2bfloat16(v);               // round-to-nearest
    float r = v - __bfloat162float(h1);                    // exact residual
    g_ws[0][idx] = h1;
    g_ws[1][idx] = __float2bfloat16(r);
}

__global__ void __launch_bounds__(NTHR, 1)
router_hmma(const float* __restrict__ x,
            float* __restrict__ scores, float* __restrict__ wout,
            float* __restrict__ iout)
{
    extern __shared__ __align__(16) char sm[];
    const uint32_t smb = smem_u32(sm);

    const int tid = threadIdx.x;
    const int l   = tid & 31;
    const int w   = tid >> 5;
    const int mt  = w & 3;          // m-tile group: rows mt*32 .. +31
    const int nh  = w >> 2;         // n-half: experts nh*32 .. +31
    const int row0 = blockIdx.x * TM;

    float acc[2][4][4];
#pragma unroll
    for (int t = 0; t < 2; t++)
#pragma unroll
        for (int n = 0; n < 4; n++)
#pragma unroll
            for (int i = 0; i < 4; i++) acc[t][n][i] = 0.f;

    // ldmatrix lane-address bases (relative to buffer start)
    const uint32_t a_rel = (uint32_t)((mt * 32 + (l & 15)) * APITCH + (l >> 4) * 16);
    const uint32_t b_rel = (uint32_t)(SM_B0 +
        (nh * 32 + (l & 7) + ((l >> 4) & 1) * 8) * APITCH + ((l >> 3) & 1) * 16);

    // ---- x loader: warp w covers rows [w*16, w*16+16); per instr j, lanes read
    //      512B contiguous (2 rows x 256B; lane = one float4 quarter) ----
    const int xr   = (l >> 4);          // row-within-pair
    const int xq   = (l & 15);          // 16B quarter within the 256B row-chunk
    const float* xbase = x + (size_t)(row0 + w * 16 + xr) * HDIM + xq * 4;
    const uint32_t aoff = (uint32_t)((w * 16 + xr) * APITCH + xq * 8);

    // ---- B loader (cp.async): lanes 0-7 cover one expert row's 128B chunk ----
    const char* bgsrc[4];
    uint32_t    bsoff[4];
#pragma unroll
    for (int p = 0; p < 4; p++) {
        int g  = w * 16 + p * 4 + (l >> 3);   // 0..127 expert-row id
        int sp = g >> 6;
        int e  = g & 63;
        bgsrc[p] = (const char*)(g_ws[sp] + (size_t)e * HDIM) + (l & 7) * 16;
        bsoff[p] = (uint32_t)(SM_B0 + sp * B_SPLIT + e * APITCH + (l & 7) * 16);
    }

    float4 xv[8];

    // ---- prologue: B chunk0 via cp.async; x chunk0 -> convert -> buf0 ----
#pragma unroll
    for (int p = 0; p < 4; p++) CP_ASYNC16(smb + bsoff[p], bgsrc[p]);
    CP_COMMIT();
#pragma unroll
    for (int j = 0; j < 8; j++)
        xv[j] = *(const float4*)(xbase + (size_t)(j * 2) * HDIM);
    {
        char* buf = sm;
#pragma unroll
        for (int j = 0; j < 8; j++) {
            float4 f = xv[j];
            uint32_t u1 = pack_rn(f.x, f.y), v1 = pack_rn(f.z, f.w);
            uint32_t u2 = pack_rn(f.x - __uint_as_float(u1 << 16),
                                  f.y - __uint_as_float(u1 & 0xFFFF0000u));
            uint32_t v2 = pack_rn(f.z - __uint_as_float(v1 << 16),
                                  f.w - __uint_as_float(v1 & 0xFFFF0000u));
            uint2 s1 = {u1, v1}, s2 = {u2, v2};
            *(uint2*)(buf + aoff + j * (2 * APITCH))           = s1;
            *(uint2*)(buf + A_SPLIT + aoff + j * (2 * APITCH)) = s2;
        }
    }
    // prefetch x chunk 1
#pragma unroll
    for (int j = 0; j < 8; j++)
        xv[j] = *(const float4*)(xbase + (size_t)(j * 2) * HDIM + KC);
    CP_WAIT0();
    __syncthreads();

    for (int c = 0; c < NCHUNK; c++) {
        const uint32_t bufb = smb + (uint32_t)((c & 1) * BUF_BYTES);
        char* nbuf = sm + ((c + 1) & 1) * BUF_BYTES;
        const uint32_t nbufb = smb + (uint32_t)(((c + 1) & 1) * BUF_BYTES);

        // ---- issue B cp.async for chunk c+1 early (overlaps MMA phase) ----
        if (c + 1 < NCHUNK) {
#pragma unroll
            for (int p = 0; p < 4; p++)
                CP_ASYNC16(nbufb + bsoff[p], bgsrc[p] + (size_t)(c + 1) * (KC * 2));
            CP_COMMIT();
        }

#pragma unroll
        for (int ks = 0; ks < 4; ks++) {
            uint32_t A0[8], A1[8], B0[8], B1[8];
            ldsm4(A0,     bufb + a_rel + ks * 32);
            ldsm4(A0 + 4, bufb + a_rel + 2304 + ks * 32);            // +16 rows
            ldsm4(A1,     bufb + A_SPLIT + a_rel + ks * 32);
            ldsm4(A1 + 4, bufb + A_SPLIT + a_rel + 2304 + ks * 32);
            ldsm4(B0,     bufb + b_rel + ks * 32);
            ldsm4(B0 + 4, bufb + b_rel + 2304 + ks * 32);
            ldsm4(B1,     bufb + B_SPLIT + b_rel + ks * 32);
            ldsm4(B1 + 4, bufb + B_SPLIT + b_rel + 2304 + ks * 32);

            // product-outer order: 8 independent accumulators between reuses
#pragma unroll
            for (int t = 0; t < 2; t++)
#pragma unroll
                for (int n = 0; n < 4; n++) mma16816(acc[t][n], A0 + t * 4, B0 + n * 2);
#pragma unroll
            for (int t = 0; t < 2; t++)
#pragma unroll
                for (int n = 0; n < 4; n++) mma16816(acc[t][n], A0 + t * 4, B1 + n * 2);
#pragma unroll
            for (int t = 0; t < 2; t++)
#pragma unroll
                for (int n = 0; n < 4; n++) mma16816(acc[t][n], A1 + t * 4, B0 + n * 2);

            if (ks == 0) {
                // ---- convert + store A chunk c+1 into the other buffer ----
                if (c + 1 < NCHUNK) {
#pragma unroll
                    for (int j = 0; j < 8; j++) {
                        float4 f = xv[j];
                        uint32_t u1 = pack_rn(f.x, f.y), v1 = pack_rn(f.z, f.w);
                        uint32_t u2 = pack_rn(f.x - __uint_as_float(u1 << 16),
                                              f.y - __uint_as_float(u1 & 0xFFFF0000u));
                        uint32_t v2 = pack_rn(f.z - __uint_as_float(v1 << 16),
                                              f.w - __uint_as_float(v1 & 0xFFFF0000u));
                        uint2 s1 = {u1, v1}, s2 = {u2, v2};
                        *(uint2*)(nbuf + aoff + j * (2 * APITCH))           = s1;
                        *(uint2*)(nbuf + A_SPLIT + aoff + j * (2 * APITCH)) = s2;
                    }
                }
                // ---- prefetch x chunk c+2 ----
                if (c + 2 < NCHUNK) {
#pragma unroll
                    for (int j = 0; j < 8; j++)
                        xv[j] = *(const float4*)(xbase + (size_t)(j * 2) * HDIM
                                                 + (size_t)(c + 2) * KC);
                }
            }
        }
        if (c + 1 < NCHUNK) { CP_WAIT0(); }
        __syncthreads();   // stores/cp.async for c+1 visible; all ldsm of c done
    }

    // ---- scatter accumulators (logits) to smem (buf0 region) ----
    float* ls = (float*)sm;
#pragma unroll
    for (int t = 0; t < 2; t++)
#pragma unroll
        for (int n = 0; n < 4; n++)
#pragma unroll
            for (int i = 0; i < 4; i++) {
                int r  = mt * 32 + t * 16 + (l >> 2) + (i >> 1) * 8;
                int cc = nh * 32 + n * 8 + (l & 3) * 2 + (i & 1);
                ls[r * LPITCH + cc] = acc[t][n][i];
            }
    __syncthreads();

    // ---- per-row softmax + top-2 + p1 norm (threads 0..127 own rows) ----
    if (tid < TM) {
        const int row = row0 + tid;
        float d[64];
#pragma unroll
        for (int e = 0; e < 64; e++) d[e] = ls[tid * LPITCH + e];

        float mx = d[0];
#pragma unroll
        for (int e = 1; e < 64; e++) mx = fmaxf(mx, d[e]);
        float sum = 0.f;
#pragma unroll
        for (int e = 0; e < 64; e++) sum += expf(d[e] - mx);
        const float inv = 1.f / sum;

        float v1 = -INFINITY, v2 = -INFINITY; int i1 = 0, i2 = 0;
#pragma unroll
        for (int e = 0; e < 64; e++) {
            float lg = d[e];
            if (lg > v1)      { v2 = v1; i2 = i1; v1 = lg; i1 = e; }
            else if (lg > v2) { v2 = lg; i2 = e; }
        }

        float* srow = scores + (size_t)row * NEXP;
#pragma unroll
        for (int q = 0; q < 16; q++) {
            float4 o;
            o.x = expf(d[4 * q + 0] - mx) * inv;
            o.y = expf(d[4 * q + 1] - mx) * inv;
            o.z = expf(d[4 * q + 2] - mx) * inv;
            o.w = expf(d[4 * q + 3] - mx) * inv;
            ((float4*)srow)[q] = o;
        }

        const float p1 = expf(v1 - mx) * inv;
        const float p2 = expf(v2 - mx) * inv;
        const float ns = 1.f / (p1 + p2);
        wout[row * 2 + 0] = p1 * ns;
        wout[row * 2 + 1] = p2 * ns;
        iout[row * 2 + 0] = (float)i1;
        iout[row * 2 + 1] = (float)i2;
    }
}

extern "C" void kernel_launch(void* const* d_in, const int* in_sizes, int n_in,
                              void* d_out, int out_size)
{
    const float* x = (const float*)d_in[0];
    const float* W = (const float*)d_in[1];

    float* out    = (float*)d_out;
    float* scores = out;                          // [N, E]
    float* wout   = out + (size_t)NROWS * NEXP;   // [N, 2]
    float* iout   = wout + (size_t)NROWS * 2;     // [N, 2] (value-cast indices)

    cudaFuncSetAttribute(router_hmma,
                         cudaFuncAttributeMaxDynamicSharedMemorySize, SM_TOTAL);

    split_w_kernel<<<(NEXP * HDIM + 255) / 256, 256>>>(W);
    router_hmma<<<NBLK, NTHR, SM_TOTAL>>>(x, scores, wout, iout);
}

// round 16
// speedup vs baseline: 3.4449x; 1.0032x over previous
#include <cuda_runtime.h>
#include <cuda_bf16.h>
#include <cstdint>
#include <math.h>

#define NROWS 16384
#define HDIM  4096
#define NEXP  64
#define KC    64
#define NCHUNK (HDIM / KC)      // 64
#define TM    128               // rows per block
#define NTHR  512               // 16 warps
#define NBLK  (NROWS / TM)      // 128 blocks, single wave

#define APITCH  144             // bytes per smem row (64 bf16 + 16B pad)
#define A_SPLIT (TM * APITCH)   // 18432 B per A split
#define B_SPLIT (NEXP * APITCH) // 9216 B per B split
#define SM_B0   (2 * A_SPLIT)   // 36864 (B region within one buffer)
#define BUF_BYTES (2 * A_SPLIT + 2 * B_SPLIT)   // 55296 per stage
#define SM_TOTAL (2 * BUF_BYTES)                 // 110592
#define LPITCH  65              // logits smem pitch (floats)

// Pre-split W: 2 bf16 terms (round-to-nearest), [split][e*HDIM + k]. 1 MB.
__device__ __nv_bfloat16 g_ws[2][NEXP * HDIM];

__device__ __forceinline__ uint32_t smem_u32(const void* p) {
    uint32_t a;
    asm("{ .reg .u64 t; cvta.to.shared.u64 t, %1; cvt.u32.u64 %0, t; }" : "=r"(a) : "l"(p));
    return a;
}
__device__ __forceinline__ void ldsm4(uint32_t* r, uint32_t addr) {
    asm volatile("ldmatrix.sync.aligned.m8n8.x4.shared.b16 {%0,%1,%2,%3}, [%4];"
                 : "=r"(r[0]), "=r"(r[1]), "=r"(r[2]), "=r"(r[3]) : "r"(addr));
}
__device__ __forceinline__ void mma16816(float* c, const uint32_t* a, const uint32_t* b) {
    asm volatile("mma.sync.aligned.m16n8k16.row.col.f32.bf16.bf16.f32 "
                 "{%0,%1,%2,%3}, {%4,%5,%6,%7}, {%8,%9}, {%0,%1,%2,%3};"
                 : "+f"(c[0]), "+f"(c[1]), "+f"(c[2]), "+f"(c[3])
                 : "r"(a[0]), "r"(a[1]), "r"(a[2]), "r"(a[3]), "r"(b[0]), "r"(b[1]));
}
__device__ __forceinline__ uint32_t pack_rn(float f0, float f1) {
    uint32_t r;
    asm("cvt.rn.bf16x2.f32 %0, %1, %2;" : "=r"(r) : "f"(f1), "f"(f0));
    return r;
}
#define CP_ASYNC16(dst, src) \
    asm volatile("cp.async.cg.shared.global [%0], [%1], 16;" :: "r"(dst), "l"(src) : "memory")
#define CP_COMMIT() asm volatile("cp.async.commit_group;" ::: "memory")
#define CP_WAIT0()  asm volatile("cp.async.wait_group 0;" ::: "memory")

__global__ void split_w_kernel(const float* __restrict__ W) {
    int idx = blockIdx.x * 256 + threadIdx.x;
    if (idx >= NEXP * HDIM) return;
    float v = W[idx];
    __nv_bfloat16 h1 = __float2bfloat16(v);               // round-to-nearest
    float r = v - __bfloat162float(h1);                    // exact residual
    g_ws[0][idx] = h1;
    g_ws[1][idx] = __float2bfloat16(r);
}

__global__ void __launch_bounds__(NTHR, 1)
router_hmma(const float* __restrict__ x,
            float* __restrict__ scores, float* __restrict__ wout,
            float* __restrict__ iout)
{
    extern __shared__ __align__(16) char sm[];
    const uint32_t smb = smem_u32(sm);

    const int tid = threadIdx.x;
    const int l   = tid & 31;
    const int w   = tid >> 5;
    const int mt  = w & 3;          // m-tile: rows mt*32 .. +31
    const int nq  = w >> 2;         // n-tile: experts nq*16 .. +15
    const int row0 = blockIdx.x * TM;

    float acc[2][2][4];
#pragma unroll
    for (int t = 0; t < 2; t++)
#pragma unroll
        for (int n = 0; n < 2; n++)
#pragma unroll
            for (int i = 0; i < 4; i++) acc[t][n][i] = 0.f;

    // ldmatrix lane-address bases (relative to buffer start)
    const uint32_t a_rel = (uint32_t)((mt * 32 + (l & 15)) * APITCH + (l >> 4) * 16);
    const uint32_t b_rel = (uint32_t)(SM_B0 +
        (nq * 16 + (l & 7) + ((l >> 4) & 1) * 8) * APITCH + ((l >> 3) & 1) * 16);

    // ---- x loader: warp w covers rows [w*8, w*8+8); per instr j, lanes read
    //      512B contiguous (2 rows x 256B; lane = one float4 quarter) ----
    const int xr = (l >> 4);        // row-within-pair
    const int xq = (l & 15);        // 16B quarter within the 256B row-chunk
    const float* xbase = x + (size_t)(row0 + w * 8 + xr) * HDIM + xq * 4;
    const uint32_t aoff = (uint32_t)((w * 8 + xr) * APITCH + xq * 8);

    // ---- B loader (cp.async): 2 x 16B per thread; 4-lane groups cover 128B rows ----
    const char* bgsrc[2];
    uint32_t    bsoff[2];
#pragma unroll
    for (int p = 0; p < 2; p++) {
        int piece = tid + p * NTHR;        // 0..1023
        int sp = piece >> 9;
        int rem = piece & 511;
        int e = rem >> 3;
        int q = rem & 7;
        bgsrc[p] = (const char*)(g_ws[sp] + (size_t)e * HDIM) + q * 16;
        bsoff[p] = (uint32_t)(SM_B0 + sp * B_SPLIT + e * APITCH + q * 16);
    }

    float4 xv[4];

    // ---- prologue: B chunk0 via cp.async; x chunk0 -> convert -> buf0 ----
#pragma unroll
    for (int p = 0; p < 2; p++) CP_ASYNC16(smb + bsoff[p], bgsrc[p]);
    CP_COMMIT();
#pragma unroll
    for (int j = 0; j < 4; j++)
        xv[j] = *(const float4*)(xbase + (size_t)(j * 2) * HDIM);
    {
        char* buf = sm;
#pragma unroll
        for (int j = 0; j < 4; j++) {
            float4 f = xv[j];
            uint32_t u1 = pack_rn(f.x, f.y), v1 = pack_rn(f.z, f.w);
            uint32_t u2 = pack_rn(f.x - __uint_as_float(u1 << 16),
                                  f.y - __uint_as_float(u1 & 0xFFFF0000u));
            uint32_t v2 = pack_rn(f.z - __uint_as_float(v1 << 16),
                                  f.w - __uint_as_float(v1 & 0xFFFF0000u));
            uint2 s1 = {u1, v1}, s2 = {u2, v2};
            *(uint2*)(buf + aoff + j * (2 * APITCH))           = s1;
            *(uint2*)(buf + A_SPLIT + aoff + j * (2 * APITCH)) = s2;
        }
    }
    // prefetch x chunk 1
#pragma unroll
    for (int j = 0; j < 4; j++)
        xv[j] = *(const float4*)(xbase + (size_t)(j * 2) * HDIM + KC);
    CP_WAIT0();
    __syncthreads();

    for (int c = 0; c < NCHUNK; c++) {
        const uint32_t bufb = smb + (uint32_t)((c & 1) * BUF_BYTES);
        char* nbuf = sm + ((c + 1) & 1) * BUF_BYTES;
        const uint32_t nbufb = smb + (uint32_t)(((c + 1) & 1) * BUF_BYTES);

        // ---- issue B cp.async for chunk c+1 early (overlaps MMA phase) ----
        if (c + 1 < NCHUNK) {
#pragma unroll
            for (int p = 0; p < 2; p++)
                CP_ASYNC16(nbufb + bsoff[p], bgsrc[p] + (size_t)(c + 1) * (KC * 2));
            CP_COMMIT();
        }

#pragma unroll
        for (int ks = 0; ks < 4; ks++) {
            uint32_t A0[8], A1[8], B0[4], B1[4];
            ldsm4(A0,     bufb + a_rel + ks * 32);
            ldsm4(A0 + 4, bufb + a_rel + 2304 + ks * 32);            // +16 rows
            ldsm4(A1,     bufb + A_SPLIT + a_rel + ks * 32);
            ldsm4(A1 + 4, bufb + A_SPLIT + a_rel + 2304 + ks * 32);
            ldsm4(B0,     bufb + b_rel + ks * 32);
            ldsm4(B1,     bufb + B_SPLIT + b_rel + ks * 32);

            // product-outer order: 4 independent accumulators between reuses
#pragma unroll
            for (int t = 0; t < 2; t++)
#pragma unroll
                for (int n = 0; n < 2; n++) mma16816(acc[t][n], A0 + t * 4, B0 + n * 2);
#pragma unroll
            for (int t = 0; t < 2; t++)
#pragma unroll
                for (int n = 0; n < 2; n++) mma16816(acc[t][n], A0 + t * 4, B1 + n * 2);
#pragma unroll
            for (int t = 0; t < 2; t++)
#pragma unroll
                for (int n = 0; n < 2; n++) mma16816(acc[t][n], A1 + t * 4, B0 + n * 2);

            if (ks == 0) {
                // ---- convert + store A chunk c+1 into the other buffer ----
                if (c + 1 < NCHUNK) {
#pragma unroll
                    for (int j = 0; j < 4; j++) {
                        float4 f = xv[j];
                        uint32_t u1 = pack_rn(f.x, f.y), v1 = pack_rn(f.z, f.w);
                        uint32_t u2 = pack_rn(f.x - __uint_as_float(u1 << 16),
                                              f.y - __uint_as_float(u1 & 0xFFFF0000u));
                        uint32_t v2 = pack_rn(f.z - __uint_as_float(v1 << 16),
                                              f.w - __uint_as_float(v1 & 0xFFFF0000u));
                        uint2 s1 = {u1, v1}, s2 = {u2, v2};
                        *(uint2*)(nbuf + aoff + j * (2 * APITCH))           = s1;
                        *(uint2*)(nbuf + A_SPLIT + aoff + j * (2 * APITCH)) = s2;
                    }
                }
                // ---- prefetch x chunk c+2 ----
                if (c + 2 < NCHUNK) {
#pragma unroll
                    for (int j = 0; j < 4; j++)
                        xv[j] = *(const float4*)(xbase + (size_t)(j * 2) * HDIM
                                                 + (size_t)(c + 2) * KC);
                }
            }
        }
        if (c + 1 < NCHUNK) { CP_WAIT0(); }
        __syncthreads();   // stores/cp.async for c+1 visible; all ldsm of c done
    }

    // ---- scatter accumulators (logits) to smem (buf0 region) ----
    float* ls = (float*)sm;
#pragma unroll
    for (int t = 0; t < 2; t++)
#pragma unroll
        for (int n = 0; n < 2; n++)
#pragma unroll
            for (int i = 0; i < 4; i++) {
                int r  = mt * 32 + t * 16 + (l >> 2) + (i >> 1) * 8;
                int cc = nq * 16 + n * 8 + (l & 3) * 2 + (i & 1);
                ls[r * LPITCH + cc] = acc[t][n][i];
            }
    __syncthreads();

    // ---- per-row softmax + top-2 + p1 norm (threads 0..127 own rows) ----
    if (tid < TM) {
        const int row = row0 + tid;
        float d[64];
#pragma unroll
        for (int e = 0; e < 64; e++) d[e] = ls[tid * LPITCH + e];

        float mx = d[0];
#pragma unroll
        for (int e = 1; e < 64; e++) mx = fmaxf(mx, d[e]);
        float sum = 0.f;
#pragma unroll
        for (int e = 0; e < 64; e++) sum += expf(d[e] - mx);
        const float inv = 1.f / sum;

        float v1 = -INFINITY, v2 = -INFINITY; int i1 = 0, i2 = 0;
#pragma unroll
        for (int e = 0; e < 64; e++) {
            float lg = d[e];
            if (lg > v1)      { v2 = v1; i2 = i1; v1 = lg; i1 = e; }
            else if (lg > v2) { v2 = lg; i2 = e; }
        }

        float* srow = scores + (size_t)row * NEXP;
#pragma unroll
        for (int q = 0; q < 16; q++) {
            float4 o;
            o.x = expf(d[4 * q + 0] - mx) * inv;
            o.y = expf(d[4 * q + 1] - mx) * inv;
            o.z = expf(d[4 * q + 2] - mx) * inv;
            o.w = expf(d[4 * q + 3] - mx) * inv;
            ((float4*)srow)[q] = o;
        }

        const float p1 = expf(v1 - mx) * inv;
        const float p2 = expf(v2 - mx) * inv;
        const float ns = 1.f / (p1 + p2);
        wout[row * 2 + 0] = p1 * ns;
        wout[row * 2 + 1] = p2 * ns;
        iout[row * 2 + 0] = (float)i1;
        iout[row * 2 + 1] = (float)i2;
    }
}

extern "C" void kernel_launch(void* const* d_in, const int* in_sizes, int n_in,
                              void* d_out, int out_size)
{
    const float* x = (const float*)d_in[0];
    const float* W = (const float*)d_in[1];

    float* out    = (float*)d_out;
    float* scores = out;                          // [N, E]
    float* wout   = out + (size_t)NROWS * NEXP;   // [N, 2]
    float* iout   = wout + (size_t)NROWS * 2;     // [N, 2] (value-cast indices)

    cudaFuncSetAttribute(router_hmma,
                         cudaFuncAttributeMaxDynamicSharedMemorySize, SM_TOTAL);

    split_w_kernel<<<(NEXP * HDIM + 255) / 256, 256>>>(W);
    router_hmma<<<NBLK, NTHR, SM_TOTAL>>>(x, scores, wout, iout);
}